// round 2
// baseline (speedup 1.0000x reference)
#include <cuda_runtime.h>

#define NN 50000
#define NE 600000
#define DD 128
#define DE 32

// Scratch (device globals — no allocation allowed)
__device__ float g_agg[NN * DD];
__device__ float g_h[NN * DD];
__device__ float g_t[NN * DD];

// ---------------------------------------------------------------------------
// float4 copy: agg = src
// ---------------------------------------------------------------------------
__global__ void copy4_kernel(const float4* __restrict__ s, float4* __restrict__ d, int n4) {
    int i = blockIdx.x * blockDim.x + threadIdx.x;
    if (i < n4) d[i] = s[i];
}

// ---------------------------------------------------------------------------
// Fused edge kernel: for each edge e:
//   msg = relu(x[src] + edge_attr[e] @ we + be);  agg[dst] += msg (atomic)
// One warp per edge (grid-stride). we (32x128 fp32, 16KB) cached in smem.
// NOTE: edge_index is int32 (JAX x64 disabled downcasts int64 -> int32).
// ---------------------------------------------------------------------------
__global__ void edge_kernel(const float* __restrict__ x,
                            const int* __restrict__ ei,
                            const float* __restrict__ ea,
                            const float4* __restrict__ we,   // [32][128] as float4[32][32]
                            const float4* __restrict__ be,   // [128] as float4[32]
                            float* __restrict__ agg) {
    __shared__ float4 we_s[DE * 32];
    for (int i = threadIdx.x; i < DE * 32; i += blockDim.x) we_s[i] = we[i];
    __syncthreads();

    const int lane = threadIdx.x & 31;
    const int warp0 = (blockIdx.x * blockDim.x + threadIdx.x) >> 5;
    const int nwarps = (gridDim.x * blockDim.x) >> 5;
    const float4 b4 = be[lane];

    for (int e = warp0; e < NE; e += nwarps) {
        int src = ei[e];
        int dst = ei[NE + e];
        // gather 4 contiguous channels per lane (coalesced 512B per warp)
        float4 x4 = ((const float4*)x)[(long long)src * 32 + lane];
        float av = ea[e * DE + lane];  // lane k holds edge_attr[e][k]
        float4 acc = b4;
#pragma unroll
        for (int k = 0; k < DE; k++) {
            float a = __shfl_sync(0xffffffffu, av, k);
            float4 w = we_s[k * 32 + lane];
            acc.x = fmaf(a, w.x, acc.x);
            acc.y = fmaf(a, w.y, acc.y);
            acc.z = fmaf(a, w.z, acc.z);
            acc.w = fmaf(a, w.w, acc.w);
        }
        float mx = fmaxf(x4.x + acc.x, 0.f);
        float my = fmaxf(x4.y + acc.y, 0.f);
        float mz = fmaxf(x4.z + acc.z, 0.f);
        float mw = fmaxf(x4.w + acc.w, 0.f);
        float* p = agg + (long long)dst * DD + (lane << 2);
        asm volatile("red.global.add.v4.f32 [%0], {%1,%2,%3,%4};"
                     :: "l"(p), "f"(mx), "f"(my), "f"(mz), "f"(mw) : "memory");
    }
}

// ---------------------------------------------------------------------------
// Tiled SGEMM: out[M,128] = act(A[M,128] @ W[128,128] + bias)
// BM=128, BN=128, BK=16, 256 threads, 8x8 micro-tile per thread.
// ---------------------------------------------------------------------------
template <bool RELU>
__global__ void mlp_gemm(const float* __restrict__ A, const float* __restrict__ W,
                         const float* __restrict__ bias, float* __restrict__ out, int M) {
    __shared__ float As[16][128];  // As[k][m]  (A tile transposed)
    __shared__ float Bs[16][128];  // Bs[k][n]

    const int tid = threadIdx.x;
    const int tx = tid & 15;   // n-tile
    const int ty = tid >> 4;   // m-tile
    const int row0 = blockIdx.x * 128;

    float acc[8][8];
#pragma unroll
    for (int i = 0; i < 8; i++)
#pragma unroll
        for (int j = 0; j < 8; j++) acc[i][j] = 0.f;

    for (int k0 = 0; k0 < 128; k0 += 16) {
#pragma unroll
        for (int l = 0; l < 2; l++) {
            int idx = tid + l * 256;   // 0..511
            // A tile: 128 rows x 16 k  (512 float4)
            int r  = idx >> 2;
            int c4 = idx & 3;
            float4 v = make_float4(0.f, 0.f, 0.f, 0.f);
            int grow = row0 + r;
            if (grow < M) v = ((const float4*)A)[(long long)grow * 32 + (k0 >> 2) + c4];
            As[c4 * 4 + 0][r] = v.x;
            As[c4 * 4 + 1][r] = v.y;
            As[c4 * 4 + 2][r] = v.z;
            As[c4 * 4 + 3][r] = v.w;
            // B tile: 16 k x 128 n (512 float4)
            int k  = idx >> 5;
            int n4 = idx & 31;
            ((float4*)&Bs[k][0])[n4] = ((const float4*)W)[(k0 + k) * 32 + n4];
        }
        __syncthreads();
#pragma unroll
        for (int k = 0; k < 16; k++) {
            float4 a0 = ((const float4*)&As[k][0])[ty * 2];
            float4 a1 = ((const float4*)&As[k][0])[ty * 2 + 1];
            float4 b0 = ((const float4*)&Bs[k][0])[tx * 2];
            float4 b1 = ((const float4*)&Bs[k][0])[tx * 2 + 1];
            float av[8] = {a0.x, a0.y, a0.z, a0.w, a1.x, a1.y, a1.z, a1.w};
            float bv[8] = {b0.x, b0.y, b0.z, b0.w, b1.x, b1.y, b1.z, b1.w};
#pragma unroll
            for (int i = 0; i < 8; i++)
#pragma unroll
                for (int j = 0; j < 8; j++) acc[i][j] = fmaf(av[i], bv[j], acc[i][j]);
        }
        __syncthreads();
    }

    float4 bb0 = ((const float4*)bias)[tx * 2];
    float4 bb1 = ((const float4*)bias)[tx * 2 + 1];
    float bvv[8] = {bb0.x, bb0.y, bb0.z, bb0.w, bb1.x, bb1.y, bb1.z, bb1.w};
#pragma unroll
    for (int i = 0; i < 8; i++) {
        int r = row0 + ty * 8 + i;
        if (r < M) {
            float o[8];
#pragma unroll
            for (int j = 0; j < 8; j++) {
                o[j] = acc[i][j] + bvv[j];
                if (RELU) o[j] = fmaxf(o[j], 0.f);
            }
            float4* po = (float4*)(out + (long long)r * DD);
            po[tx * 2]     = make_float4(o[0], o[1], o[2], o[3]);
            po[tx * 2 + 1] = make_float4(o[4], o[5], o[6], o[7]);
        }
    }
}

// ---------------------------------------------------------------------------
extern "C" void kernel_launch(void* const* d_in, const int* in_sizes, int n_in,
                              void* d_out, int out_size) {
    const float* x    = (const float*)d_in[0];
    const int*   ei   = (const int*)d_in[1];      // int32 (JAX default x64-disabled)
    const float* ea   = (const float*)d_in[2];
    const float* w1_0 = (const float*)d_in[3];
    const float* b1_0 = (const float*)d_in[4];
    const float* w2_0 = (const float*)d_in[5];
    const float* b2_0 = (const float*)d_in[6];
    const float* we_0 = (const float*)d_in[7];
    const float* be_0 = (const float*)d_in[8];
    const float* w1_1 = (const float*)d_in[9];
    const float* b1_1 = (const float*)d_in[10];
    const float* w2_1 = (const float*)d_in[11];
    const float* b2_1 = (const float*)d_in[12];
    const float* we_1 = (const float*)d_in[13];
    const float* be_1 = (const float*)d_in[14];
    const float* fc1w = (const float*)d_in[15];
    const float* fc1b = (const float*)d_in[16];
    const float* fc2w = (const float*)d_in[17];
    const float* fc2b = (const float*)d_in[18];
    float* out = (float*)d_out;

    float *agg, *h, *t;
    cudaGetSymbolAddress((void**)&agg, g_agg);
    cudaGetSymbolAddress((void**)&h,   g_h);
    cudaGetSymbolAddress((void**)&t,   g_t);

    const int n4 = NN * (DD / 4);
    const int copyBlocks = (n4 + 255) / 256;
    const int edgeBlocks = 1776;                 // grid-stride; ~12 blocks/SM launched
    const int gemmBlocks = (NN + 127) / 128;     // 391

    // ---- Layer 0 ----
    copy4_kernel<<<copyBlocks, 256>>>((const float4*)x, (float4*)agg, n4);
    edge_kernel<<<edgeBlocks, 256>>>(x, ei, ea, (const float4*)we_0, (const float4*)be_0, agg);
    mlp_gemm<true><<<gemmBlocks, 256>>>(agg, w1_0, b1_0, t, NN);
    mlp_gemm<true><<<gemmBlocks, 256>>>(t, w2_0, b2_0, h, NN);   // + inter-layer relu

    // ---- Layer 1 ----
    copy4_kernel<<<copyBlocks, 256>>>((const float4*)h, (float4*)agg, n4);
    edge_kernel<<<edgeBlocks, 256>>>(h, ei, ea, (const float4*)we_1, (const float4*)be_1, agg);
    mlp_gemm<true><<<gemmBlocks, 256>>>(agg, w1_1, b1_1, t, NN);
    mlp_gemm<true><<<gemmBlocks, 256>>>(t, w2_1, b2_1, h, NN);   // + inter-layer relu

    // ---- Head ----
    mlp_gemm<true><<<gemmBlocks, 256>>>(h, fc1w, fc1b, t, NN);
    mlp_gemm<false><<<gemmBlocks, 256>>>(t, fc2w, fc2b, out, NN);
}

// round 4
// speedup vs baseline: 1.0125x; 1.0125x over previous
#include <cuda_runtime.h>

#define NN 50000
#define NE 600000
#define DD 128
#define DE 32

// Scratch (device globals — no allocation allowed)
__device__ float g_agg[NN * DD];
__device__ float g_h[NN * DD];
__device__ float g_t[NN * DD];

typedef unsigned long long u64;

// ---- packed fp32x2 helpers (sm_103a FFMA2 path; ptxas never auto-fuses) ----
__device__ __forceinline__ u64 ffma2(u64 a, u64 b, u64 c) {
    u64 d;
    asm("fma.rn.f32x2 %0, %1, %2, %3;" : "=l"(d) : "l"(a), "l"(b), "l"(c));
    return d;
}
__device__ __forceinline__ u64 fadd2(u64 a, u64 b) {
    u64 d;
    asm("add.rn.f32x2 %0, %1, %2;" : "=l"(d) : "l"(a), "l"(b));
    return d;
}
__device__ __forceinline__ u64 pack2(float lo, float hi) {
    u64 d;
    asm("mov.b64 %0, {%1, %2};" : "=l"(d) : "f"(lo), "f"(hi));
    return d;
}
__device__ __forceinline__ void unpack2(u64 v, float& lo, float& hi) {
    asm("mov.b64 {%0, %1}, %2;" : "=f"(lo), "=f"(hi) : "l"(v));
}

// ---------------------------------------------------------------------------
// float4 copy: agg = src
// ---------------------------------------------------------------------------
__global__ void copy4_kernel(const float4* __restrict__ s, float4* __restrict__ d, int n4) {
    int i = blockIdx.x * blockDim.x + threadIdx.x;
    if (i < n4) d[i] = s[i];
}

// ---------------------------------------------------------------------------
// Fused edge kernel v2: weights register-resident, f32x2 math, no smem.
// Two warps per edge; warp (pair,half) owns output channels [half*64, half*64+64).
// Each lane owns 2 channels (one f32x2). Per k: 64-bit shfl + 1 FFMA2.
// edge_index is int32 (JAX x64-disabled downcasts int64).
// ---------------------------------------------------------------------------
__global__ void __launch_bounds__(256, 2)
edge_kernel(const float* __restrict__ x,
            const int* __restrict__ ei,
            const float* __restrict__ ea,
            const float* __restrict__ we,   // [32][128] row-major
            const float* __restrict__ be,   // [128]
            float* __restrict__ agg) {
    const int lane = threadIdx.x & 31;
    const int gw = (blockIdx.x * blockDim.x + threadIdx.x) >> 5;
    const int nwarps = (gridDim.x * blockDim.x) >> 5;   // even (multiple of 8)
    const int half = gw & 1;
    const int pair0 = gw >> 1;
    const int npairs = nwarps >> 1;
    const int base_n = half * 64 + lane * 2;

    // Load this warp's weight column slice once (persistent grid-stride warp).
    u64 wreg[DE];
#pragma unroll
    for (int k = 0; k < DE; k++)
        wreg[k] = *(const u64*)(we + k * DD + base_n);
    const u64 b2 = *(const u64*)(be + base_n);

    for (int e = pair0; e < NE; e += npairs) {
        const int src = __ldg(ei + e);
        const int dst = __ldg(ei + NE + e);
        const float av = __ldg(ea + (long long)e * DE + lane);
        const u64 av2 = pack2(av, av);
        const u64 x2 = *(const u64*)(x + (long long)src * DD + base_n);

        u64 acc = fadd2(b2, x2);     // x + bias; emb accumulates on top
#pragma unroll
        for (int k = 0; k < DE; k++) {
            u64 a2 = __shfl_sync(0xffffffffu, av2, k);
            acc = ffma2(a2, wreg[k], acc);
        }
        float lo, hi;
        unpack2(acc, lo, hi);
        lo = fmaxf(lo, 0.f);
        hi = fmaxf(hi, 0.f);
        float* p = agg + (long long)dst * DD + base_n;
        asm volatile("red.global.add.v2.f32 [%0], {%1,%2};"
                     :: "l"(p), "f"(lo), "f"(hi) : "memory");
    }
}

// ---------------------------------------------------------------------------
// Tiled SGEMM v2 (f32x2): out[M,128] = act(A[M,128] @ W[128,128] + bias)
// BM=128, BN=128, BK=16, 256 threads, 8x8 micro-tile, FFMA2 inner product.
// acc2[i2][j]: i2 = m-pair (natural 64-bit lanes of As), j = n; b duplicated
// into {b,b} registers per k (ALU pipe, off the FMA critical path).
// ---------------------------------------------------------------------------
template <bool RELU>
__global__ void __launch_bounds__(256, 2)
mlp_gemm(const float* __restrict__ A, const float* __restrict__ W,
         const float* __restrict__ bias, float* __restrict__ out, int M) {
    __shared__ float As[16][128];  // As[k][m]
    __shared__ float Bs[16][128];  // Bs[k][n]

    const int tid = threadIdx.x;
    const int tx = tid & 15;   // n-tile (8 cols)
    const int ty = tid >> 4;   // m-tile (8 rows)
    const int row0 = blockIdx.x * 128;

    u64 acc2[4][8];
#pragma unroll
    for (int i = 0; i < 4; i++)
#pragma unroll
        for (int j = 0; j < 8; j++) acc2[i][j] = 0ULL;

    for (int k0 = 0; k0 < 128; k0 += 16) {
#pragma unroll
        for (int l = 0; l < 2; l++) {
            int idx = tid + l * 256;   // 0..511
            // A tile: 128 rows x 16 k (512 float4), store transposed k-major
            int r  = idx >> 2;
            int c4 = idx & 3;
            float4 v = make_float4(0.f, 0.f, 0.f, 0.f);
            int grow = row0 + r;
            if (grow < M) v = ((const float4*)A)[(long long)grow * 32 + (k0 >> 2) + c4];
            As[c4 * 4 + 0][r] = v.x;
            As[c4 * 4 + 1][r] = v.y;
            As[c4 * 4 + 2][r] = v.z;
            As[c4 * 4 + 3][r] = v.w;
            // B tile: 16 k x 128 n (512 float4)
            int k  = idx >> 5;
            int n4 = idx & 31;
            ((float4*)&Bs[k][0])[n4] = ((const float4*)W)[(k0 + k) * 32 + n4];
        }
        __syncthreads();
#pragma unroll
        for (int k = 0; k < 16; k++) {
            // a pairs over m: 2x LDS.128 -> 4 u64 pairs, no packing needed
            const u64* ap = (const u64*)&As[k][ty * 8];
            u64 a01 = ap[0], a23 = ap[1], a45 = ap[2], a67 = ap[3];
            // b scalars: 2x LDS.128, duplicate each into {b,b}
            float4 b0 = ((const float4*)&Bs[k][0])[tx * 2];
            float4 b1 = ((const float4*)&Bs[k][0])[tx * 2 + 1];
            u64 bd[8];
            bd[0] = pack2(b0.x, b0.x); bd[1] = pack2(b0.y, b0.y);
            bd[2] = pack2(b0.z, b0.z); bd[3] = pack2(b0.w, b0.w);
            bd[4] = pack2(b1.x, b1.x); bd[5] = pack2(b1.y, b1.y);
            bd[6] = pack2(b1.z, b1.z); bd[7] = pack2(b1.w, b1.w);
            u64 av[4] = {a01, a23, a45, a67};
#pragma unroll
            for (int i = 0; i < 4; i++)
#pragma unroll
                for (int j = 0; j < 8; j++)
                    acc2[i][j] = ffma2(av[i], bd[j], acc2[i][j]);
        }
        __syncthreads();
    }

    float4 bb0 = ((const float4*)bias)[tx * 2];
    float4 bb1 = ((const float4*)bias)[tx * 2 + 1];
    float bvv[8] = {bb0.x, bb0.y, bb0.z, bb0.w, bb1.x, bb1.y, bb1.z, bb1.w};
#pragma unroll
    for (int i2 = 0; i2 < 4; i2++) {
        float o0[8], o1[8];   // rows 2*i2, 2*i2+1
#pragma unroll
        for (int j = 0; j < 8; j++) {
            float lo, hi;
            unpack2(acc2[i2][j], lo, hi);
            lo += bvv[j]; hi += bvv[j];
            if (RELU) { lo = fmaxf(lo, 0.f); hi = fmaxf(hi, 0.f); }
            o0[j] = lo; o1[j] = hi;
        }
        int r0 = row0 + ty * 8 + 2 * i2;
        if (r0 < M) {
            float4* po = (float4*)(out + (long long)r0 * DD);
            po[tx * 2]     = make_float4(o0[0], o0[1], o0[2], o0[3]);
            po[tx * 2 + 1] = make_float4(o0[4], o0[5], o0[6], o0[7]);
        }
        if (r0 + 1 < M) {
            float4* po = (float4*)(out + (long long)(r0 + 1) * DD);
            po[tx * 2]     = make_float4(o1[0], o1[1], o1[2], o1[3]);
            po[tx * 2 + 1] = make_float4(o1[4], o1[5], o1[6], o1[7]);
        }
    }
}

// ---------------------------------------------------------------------------
extern "C" void kernel_launch(void* const* d_in, const int* in_sizes, int n_in,
                              void* d_out, int out_size) {
    const float* x    = (const float*)d_in[0];
    const int*   ei   = (const int*)d_in[1];      // int32
    const float* ea   = (const float*)d_in[2];
    const float* w1_0 = (const float*)d_in[3];
    const float* b1_0 = (const float*)d_in[4];
    const float* w2_0 = (const float*)d_in[5];
    const float* b2_0 = (const float*)d_in[6];
    const float* we_0 = (const float*)d_in[7];
    const float* be_0 = (const float*)d_in[8];
    const float* w1_1 = (const float*)d_in[9];
    const float* b1_1 = (const float*)d_in[10];
    const float* w2_1 = (const float*)d_in[11];
    const float* b2_1 = (const float*)d_in[12];
    const float* we_1 = (const float*)d_in[13];
    const float* be_1 = (const float*)d_in[14];
    const float* fc1w = (const float*)d_in[15];
    const float* fc1b = (const float*)d_in[16];
    const float* fc2w = (const float*)d_in[17];
    const float* fc2b = (const float*)d_in[18];
    float* out = (float*)d_out;

    float *agg, *h, *t;
    cudaGetSymbolAddress((void**)&agg, g_agg);
    cudaGetSymbolAddress((void**)&h,   g_h);
    cudaGetSymbolAddress((void**)&t,   g_t);

    const int n4 = NN * (DD / 4);
    const int copyBlocks = (n4 + 255) / 256;
    const int edgeBlocks = 296;                  // 2 CTAs/SM resident, persistent
    const int gemmBlocks = (NN + 127) / 128;     // 391

    // ---- Layer 0 ----
    copy4_kernel<<<copyBlocks, 256>>>((const float4*)x, (float4*)agg, n4);
    edge_kernel<<<edgeBlocks, 256>>>(x, ei, ea, we_0, be_0, agg);
    mlp_gemm<true><<<gemmBlocks, 256>>>(agg, w1_0, b1_0, t, NN);
    mlp_gemm<true><<<gemmBlocks, 256>>>(t, w2_0, b2_0, h, NN);   // + inter-layer relu

    // ---- Layer 1 ----
    copy4_kernel<<<copyBlocks, 256>>>((const float4*)h, (float4*)agg, n4);
    edge_kernel<<<edgeBlocks, 256>>>(h, ei, ea, we_1, be_1, agg);
    mlp_gemm<true><<<gemmBlocks, 256>>>(agg, w1_1, b1_1, t, NN);
    mlp_gemm<true><<<gemmBlocks, 256>>>(t, w2_1, b2_1, h, NN);   // + inter-layer relu

    // ---- Head ----
    mlp_gemm<true><<<gemmBlocks, 256>>>(h, fc1w, fc1b, t, NN);
    mlp_gemm<false><<<gemmBlocks, 256>>>(t, fc2w, fc2b, out, NN);
}

// round 5
// speedup vs baseline: 1.2749x; 1.2592x over previous
#include <cuda_runtime.h>

#define NN 50000
#define NE 600000
#define DD 128
#define DE 32

typedef unsigned long long u64;

// Scratch (device globals — no allocation allowed)
__device__ float g_agg[NN * DD];
__device__ float g_h[NN * DD];
__device__ float g_t[NN * DD];
__device__ float g_msg[(size_t)NE * DD];     // 307 MB message buffer
__device__ int   g_rowptr[NN + 1];
__device__ int   g_woff[NN];
__device__ int   g_cnt[NN];
__device__ int   g_srcp[NE];                 // src permuted by dst-group
__device__ int   g_eidx[NE];                 // original edge id permuted

// ---- packed fp32x2 helpers ----
__device__ __forceinline__ u64 ffma2(u64 a, u64 b, u64 c) {
    u64 d;
    asm("fma.rn.f32x2 %0, %1, %2, %3;" : "=l"(d) : "l"(a), "l"(b), "l"(c));
    return d;
}
__device__ __forceinline__ u64 pack2(float lo, float hi) {
    u64 d;
    asm("mov.b64 %0, {%1, %2};" : "=l"(d) : "f"(lo), "f"(hi));
    return d;
}
__device__ __forceinline__ void unpack2(u64 v, float& lo, float& hi) {
    asm("mov.b64 {%0, %1}, %2;" : "=f"(lo), "=f"(hi) : "l"(v));
}

// ===========================================================================
// CSR build
// ===========================================================================
__global__ void zero_cnt_kernel() {
    int i = blockIdx.x * blockDim.x + threadIdx.x;
    if (i < NN) g_cnt[i] = 0;
}

__global__ void hist_kernel(const int* __restrict__ ei) {
    int i = blockIdx.x * blockDim.x + threadIdx.x;
    if (i < NE) atomicAdd(&g_cnt[ei[NE + i]], 1);
}

// Single-block exclusive scan of g_cnt -> g_rowptr, g_woff
__global__ void scan_kernel() {
    __shared__ int s[1024];
    const int tid = threadIdx.x;
    int running = 0;
    for (int base = 0; base < NN; base += 1024) {
        int idx = base + tid;
        int v = (idx < NN) ? g_cnt[idx] : 0;
        s[tid] = v;
        __syncthreads();
#pragma unroll
        for (int off = 1; off < 1024; off <<= 1) {
            int t = (tid >= off) ? s[tid - off] : 0;
            __syncthreads();
            s[tid] += t;
            __syncthreads();
        }
        int excl = running + s[tid] - v;
        if (idx < NN) { g_rowptr[idx] = excl; g_woff[idx] = excl; }
        running += s[1023];
        __syncthreads();
    }
    if (tid == 0) g_rowptr[NN] = running;
}

__global__ void scatter_kernel(const int* __restrict__ ei) {
    int i = blockIdx.x * blockDim.x + threadIdx.x;
    if (i < NE) {
        int d = ei[NE + i];
        int p = atomicAdd(&g_woff[d], 1);
        g_srcp[p] = ei[i];
        g_eidx[p] = i;
    }
}

// ===========================================================================
// msg kernel: msg[i] = relu(x[srcp[i]] + ea[eidx[i]] @ we + be)
// Block = 128 permuted edges x 128 out channels, K=32 single tile, FFMA2.
// ===========================================================================
__global__ void __launch_bounds__(256, 2)
msg_kernel(const float* __restrict__ xin, const float* __restrict__ ea,
           const float* __restrict__ we, const float* __restrict__ be) {
    __shared__ float Ea[DE][130];   // k-major, padded (2-way store conflicts only)
    __shared__ float Bs[DE][DD];    // we, row-major (k-major rows)

    const int tid = threadIdx.x;
    const int tx = tid & 15;
    const int ty = tid >> 4;
    const long long i0 = (long long)blockIdx.x * 128;

#pragma unroll
    for (int l = 0; l < 4; l++) {
        int idx = tid + l * 256;           // 0..1023
        // Ea: edge rows -> transposed k-major
        int r  = idx >> 3;                  // 0..127
        int c4 = idx & 7;                   // 0..7 (k/4)
        float4 v = make_float4(0.f, 0.f, 0.f, 0.f);
        long long gi = i0 + r;
        if (gi < NE) {
            int e = g_eidx[gi];
            v = ((const float4*)ea)[(long long)e * 8 + c4];
        }
        Ea[c4 * 4 + 0][r] = v.x;
        Ea[c4 * 4 + 1][r] = v.y;
        Ea[c4 * 4 + 2][r] = v.z;
        Ea[c4 * 4 + 3][r] = v.w;
        // Bs: direct copy of we [32][128]
        int k  = idx >> 5;
        int n4 = idx & 31;
        ((float4*)&Bs[k][0])[n4] = ((const float4*)we)[idx];
    }
    __syncthreads();

    u64 acc2[4][8];
#pragma unroll
    for (int i = 0; i < 4; i++)
#pragma unroll
        for (int j = 0; j < 8; j++) acc2[i][j] = 0ULL;

#pragma unroll 8
    for (int k = 0; k < DE; k++) {
        const u64* ap = (const u64*)&Ea[k][ty * 8];
        u64 av[4] = {ap[0], ap[1], ap[2], ap[3]};
        float4 b0 = ((const float4*)&Bs[k][0])[tx * 2];
        float4 b1 = ((const float4*)&Bs[k][0])[tx * 2 + 1];
        u64 bd[8];
        bd[0] = pack2(b0.x, b0.x); bd[1] = pack2(b0.y, b0.y);
        bd[2] = pack2(b0.z, b0.z); bd[3] = pack2(b0.w, b0.w);
        bd[4] = pack2(b1.x, b1.x); bd[5] = pack2(b1.y, b1.y);
        bd[6] = pack2(b1.z, b1.z); bd[7] = pack2(b1.w, b1.w);
#pragma unroll
        for (int i = 0; i < 4; i++)
#pragma unroll
            for (int j = 0; j < 8; j++)
                acc2[i][j] = ffma2(av[i], bd[j], acc2[i][j]);
    }

    float4 bb0 = ((const float4*)be)[tx * 2];
    float4 bb1 = ((const float4*)be)[tx * 2 + 1];
    float bvv[8] = {bb0.x, bb0.y, bb0.z, bb0.w, bb1.x, bb1.y, bb1.z, bb1.w};
    float* msg = g_msg;
#pragma unroll
    for (int i2 = 0; i2 < 4; i2++) {
        int r0 = ty * 8 + 2 * i2;
        long long gi0 = i0 + r0;
        float o0[8], o1[8];
#pragma unroll
        for (int j = 0; j < 8; j++) unpack2(acc2[i2][j], o0[j], o1[j]);
#pragma unroll
        for (int rr = 0; rr < 2; rr++) {
            long long gi = gi0 + rr;
            if (gi < NE) {
                int src = g_srcp[gi];
                float4 xv0 = ((const float4*)xin)[(long long)src * 32 + tx * 2];
                float4 xv1 = ((const float4*)xin)[(long long)src * 32 + tx * 2 + 1];
                float xr[8] = {xv0.x, xv0.y, xv0.z, xv0.w, xv1.x, xv1.y, xv1.z, xv1.w};
                float* o = rr ? o1 : o0;
                float res[8];
#pragma unroll
                for (int j = 0; j < 8; j++)
                    res[j] = fmaxf(o[j] + bvv[j] + xr[j], 0.f);
                float4* po = (float4*)(msg + gi * DD);
                po[tx * 2]     = make_float4(res[0], res[1], res[2], res[3]);
                po[tx * 2 + 1] = make_float4(res[4], res[5], res[6], res[7]);
            }
        }
    }
}

// ===========================================================================
// segment sum: agg[n] = x[n] + sum over msg rows rowptr[n]..rowptr[n+1]
// One warp per node; lane owns 4 channels (float4). Sequential msg reads.
// ===========================================================================
__global__ void seg_sum_kernel(const float* __restrict__ xin, float* __restrict__ agg) {
    int w = (blockIdx.x * blockDim.x + threadIdx.x) >> 5;
    int lane = threadIdx.x & 31;
    if (w >= NN) return;
    int s = g_rowptr[w];
    int e = g_rowptr[w + 1];
    const float4* m4 = (const float4*)g_msg;
    float4 a = ((const float4*)xin)[(long long)w * 32 + lane];
    float4 b = make_float4(0.f, 0.f, 0.f, 0.f);
    int r = s;
    for (; r + 1 < e; r += 2) {
        float4 u = m4[(long long)r * 32 + lane];
        float4 v = m4[(long long)(r + 1) * 32 + lane];
        a.x += u.x; a.y += u.y; a.z += u.z; a.w += u.w;
        b.x += v.x; b.y += v.y; b.z += v.z; b.w += v.w;
    }
    if (r < e) {
        float4 u = m4[(long long)r * 32 + lane];
        a.x += u.x; a.y += u.y; a.z += u.z; a.w += u.w;
    }
    a.x += b.x; a.y += b.y; a.z += b.z; a.w += b.w;
    ((float4*)agg)[(long long)w * 32 + lane] = a;
}

// ===========================================================================
// Tiled SGEMM (f32x2): out[M,128] = act(A[M,128] @ W[128,128] + bias)
// ===========================================================================
template <bool RELU>
__global__ void __launch_bounds__(256, 2)
mlp_gemm(const float* __restrict__ A, const float* __restrict__ W,
         const float* __restrict__ bias, float* __restrict__ out, int M) {
    __shared__ float As[16][128];
    __shared__ float Bs[16][128];

    const int tid = threadIdx.x;
    const int tx = tid & 15;
    const int ty = tid >> 4;
    const int row0 = blockIdx.x * 128;

    u64 acc2[4][8];
#pragma unroll
    for (int i = 0; i < 4; i++)
#pragma unroll
        for (int j = 0; j < 8; j++) acc2[i][j] = 0ULL;

    for (int k0 = 0; k0 < 128; k0 += 16) {
#pragma unroll
        for (int l = 0; l < 2; l++) {
            int idx = tid + l * 256;
            int r  = idx >> 2;
            int c4 = idx & 3;
            float4 v = make_float4(0.f, 0.f, 0.f, 0.f);
            int grow = row0 + r;
            if (grow < M) v = ((const float4*)A)[(long long)grow * 32 + (k0 >> 2) + c4];
            As[c4 * 4 + 0][r] = v.x;
            As[c4 * 4 + 1][r] = v.y;
            As[c4 * 4 + 2][r] = v.z;
            As[c4 * 4 + 3][r] = v.w;
            int k  = idx >> 5;
            int n4 = idx & 31;
            ((float4*)&Bs[k][0])[n4] = ((const float4*)W)[(k0 + k) * 32 + n4];
        }
        __syncthreads();
#pragma unroll
        for (int k = 0; k < 16; k++) {
            const u64* ap = (const u64*)&As[k][ty * 8];
            u64 av[4] = {ap[0], ap[1], ap[2], ap[3]};
            float4 b0 = ((const float4*)&Bs[k][0])[tx * 2];
            float4 b1 = ((const float4*)&Bs[k][0])[tx * 2 + 1];
            u64 bd[8];
            bd[0] = pack2(b0.x, b0.x); bd[1] = pack2(b0.y, b0.y);
            bd[2] = pack2(b0.z, b0.z); bd[3] = pack2(b0.w, b0.w);
            bd[4] = pack2(b1.x, b1.x); bd[5] = pack2(b1.y, b1.y);
            bd[6] = pack2(b1.z, b1.z); bd[7] = pack2(b1.w, b1.w);
#pragma unroll
            for (int i = 0; i < 4; i++)
#pragma unroll
                for (int j = 0; j < 8; j++)
                    acc2[i][j] = ffma2(av[i], bd[j], acc2[i][j]);
        }
        __syncthreads();
    }

    float4 bb0 = ((const float4*)bias)[tx * 2];
    float4 bb1 = ((const float4*)bias)[tx * 2 + 1];
    float bvv[8] = {bb0.x, bb0.y, bb0.z, bb0.w, bb1.x, bb1.y, bb1.z, bb1.w};
#pragma unroll
    for (int i2 = 0; i2 < 4; i2++) {
        float o0[8], o1[8];
#pragma unroll
        for (int j = 0; j < 8; j++) {
            float lo, hi;
            unpack2(acc2[i2][j], lo, hi);
            lo += bvv[j]; hi += bvv[j];
            if (RELU) { lo = fmaxf(lo, 0.f); hi = fmaxf(hi, 0.f); }
            o0[j] = lo; o1[j] = hi;
        }
        int r0 = row0 + ty * 8 + 2 * i2;
        if (r0 < M) {
            float4* po = (float4*)(out + (long long)r0 * DD);
            po[tx * 2]     = make_float4(o0[0], o0[1], o0[2], o0[3]);
            po[tx * 2 + 1] = make_float4(o0[4], o0[5], o0[6], o0[7]);
        }
        if (r0 + 1 < M) {
            float4* po = (float4*)(out + (long long)(r0 + 1) * DD);
            po[tx * 2]     = make_float4(o1[0], o1[1], o1[2], o1[3]);
            po[tx * 2 + 1] = make_float4(o1[4], o1[5], o1[6], o1[7]);
        }
    }
}

// ---------------------------------------------------------------------------
extern "C" void kernel_launch(void* const* d_in, const int* in_sizes, int n_in,
                              void* d_out, int out_size) {
    const float* x    = (const float*)d_in[0];
    const int*   ei   = (const int*)d_in[1];      // int32
    const float* ea   = (const float*)d_in[2];
    const float* w1_0 = (const float*)d_in[3];
    const float* b1_0 = (const float*)d_in[4];
    const float* w2_0 = (const float*)d_in[5];
    const float* b2_0 = (const float*)d_in[6];
    const float* we_0 = (const float*)d_in[7];
    const float* be_0 = (const float*)d_in[8];
    const float* w1_1 = (const float*)d_in[9];
    const float* b1_1 = (const float*)d_in[10];
    const float* w2_1 = (const float*)d_in[11];
    const float* b2_1 = (const float*)d_in[12];
    const float* we_1 = (const float*)d_in[13];
    const float* be_1 = (const float*)d_in[14];
    const float* fc1w = (const float*)d_in[15];
    const float* fc1b = (const float*)d_in[16];
    const float* fc2w = (const float*)d_in[17];
    const float* fc2b = (const float*)d_in[18];
    float* out = (float*)d_out;

    float *agg, *h, *t;
    cudaGetSymbolAddress((void**)&agg, g_agg);
    cudaGetSymbolAddress((void**)&h,   g_h);
    cudaGetSymbolAddress((void**)&t,   g_t);

    const int nodeBlocks = (NN + 255) / 256;          // 196
    const int edgeThreadBlocks = (NE + 255) / 256;    // 2344
    const int msgBlocks = (NE + 127) / 128;           // 4688
    const int segBlocks = (NN * 32 + 255) / 256;      // 6250
    const int gemmBlocks = (NN + 127) / 128;          // 391

    // ---- CSR build (once; reused by both layers) ----
    zero_cnt_kernel<<<nodeBlocks, 256>>>();
    hist_kernel<<<edgeThreadBlocks, 256>>>(ei);
    scan_kernel<<<1, 1024>>>();
    scatter_kernel<<<edgeThreadBlocks, 256>>>(ei);

    // ---- Layer 0 ----
    msg_kernel<<<msgBlocks, 256>>>(x, ea, we_0, be_0);
    seg_sum_kernel<<<segBlocks, 256>>>(x, agg);
    mlp_gemm<true><<<gemmBlocks, 256>>>(agg, w1_0, b1_0, t, NN);
    mlp_gemm<true><<<gemmBlocks, 256>>>(t, w2_0, b2_0, h, NN);   // + inter-layer relu

    // ---- Layer 1 ----
    msg_kernel<<<msgBlocks, 256>>>(h, ea, we_1, be_1);
    seg_sum_kernel<<<segBlocks, 256>>>(h, agg);
    mlp_gemm<true><<<gemmBlocks, 256>>>(agg, w1_1, b1_1, t, NN);
    mlp_gemm<true><<<gemmBlocks, 256>>>(t, w2_1, b2_1, h, NN);   // + inter-layer relu

    // ---- Head ----
    mlp_gemm<true><<<gemmBlocks, 256>>>(h, fc1w, fc1b, t, NN);
    mlp_gemm<false><<<gemmBlocks, 256>>>(t, fc2w, fc2b, out, NN);
}

// round 6
// speedup vs baseline: 1.5553x; 1.2200x over previous
#include <cuda_runtime.h>

#define NN 50000
#define NE 600000
#define DD 128
#define DE 32

typedef unsigned long long u64;

// Scratch (device globals — no allocation allowed)
__device__ float g_agg[NN * DD];
__device__ float g_h[NN * DD];
__device__ float g_t[NN * DD];
__device__ float g_eap[(size_t)NE * DE];     // permuted edge_attr (77 MB)
__device__ int   g_rowptr[NN + 1];
__device__ int   g_woff[NN];
__device__ int   g_cnt[NN];
__device__ int   g_srcp[NE];                 // src, permuted by dst-group
__device__ int   g_dstp[NE];                 // dst, permuted (sorted)
__device__ int   g_eidx[NE];                 // original edge id, permuted

// ---- packed fp32x2 helpers ----
__device__ __forceinline__ u64 ffma2(u64 a, u64 b, u64 c) {
    u64 d;
    asm("fma.rn.f32x2 %0, %1, %2, %3;" : "=l"(d) : "l"(a), "l"(b), "l"(c));
    return d;
}
__device__ __forceinline__ u64 pack2(float lo, float hi) {
    u64 d;
    asm("mov.b64 %0, {%1, %2};" : "=l"(d) : "f"(lo), "f"(hi));
    return d;
}
__device__ __forceinline__ void unpack2(u64 v, float& lo, float& hi) {
    asm("mov.b64 {%0, %1}, %2;" : "=f"(lo), "=f"(hi) : "l"(v));
}

// ===========================================================================
// CSR build
// ===========================================================================
__global__ void zero_cnt_kernel() {
    int i = blockIdx.x * blockDim.x + threadIdx.x;
    if (i < NN) g_cnt[i] = 0;
}

__global__ void hist_kernel(const int* __restrict__ ei) {
    int i = blockIdx.x * blockDim.x + threadIdx.x;
    if (i < NE) atomicAdd(&g_cnt[ei[NE + i]], 1);
}

// 1024 threads; each scans a 49-element chunk sequentially, then one
// Hillis-Steele over the 1024 chunk totals.
__global__ void scan_kernel() {
    __shared__ int s[1024];
    const int tid = threadIdx.x;
    const int CH = (NN + 1023) / 1024;   // 49
    const int base = tid * CH;
    const int end = min(base + CH, NN);
    int tot = 0;
    for (int i = base; i < end; i++) tot += g_cnt[i];
    s[tid] = tot;
    __syncthreads();
#pragma unroll
    for (int off = 1; off < 1024; off <<= 1) {
        int t = (tid >= off) ? s[tid - off] : 0;
        __syncthreads();
        s[tid] += t;
        __syncthreads();
    }
    int run = s[tid] - tot;              // exclusive prefix of this chunk
    for (int i = base; i < end; i++) {
        int v = g_cnt[i];
        g_rowptr[i] = run;
        g_woff[i] = run;
        run += v;
    }
    if (end == NN) g_rowptr[NN] = run;
}

__global__ void scatter_kernel(const int* __restrict__ ei) {
    int i = blockIdx.x * blockDim.x + threadIdx.x;
    if (i < NE) {
        int d = ei[NE + i];
        int p = atomicAdd(&g_woff[d], 1);
        g_srcp[p] = ei[i];
        g_dstp[p] = d;
        g_eidx[p] = i;
    }
}

// Permute edge_attr rows into CSR order (sequential writes, 128B-row reads).
__global__ void permute_ea_kernel(const float4* __restrict__ ea4) {
    long long t = (long long)blockIdx.x * blockDim.x + threadIdx.x;
    if (t < (long long)NE * 8) {
        long long i = t >> 3;
        int c = (int)(t & 7);
        int e = g_eidx[i];
        ((float4*)g_eap)[t] = ea4[(long long)e * 8 + c];
    }
}

// ===========================================================================
// Fused edge kernel: per block = 128 CSR-ordered edges x 128 channels.
//   emb = ea_perm @ we  (K=32 tile, FFMA2)
//   res = relu(emb + be + x[srcp])
//   segmented in-register sum over dst runs -> red.global.add into agg
// agg must be pre-seeded with x (copy4).
// ===========================================================================
__global__ void __launch_bounds__(256, 2)
edge_fused_kernel(const float* __restrict__ xin,
                  const float* __restrict__ we, const float* __restrict__ be,
                  float* __restrict__ agg) {
    __shared__ float Ea[DE][130];   // k-major edge-attr tile (padded)
    __shared__ float Bs[DE][DD];    // we

    const int tid = threadIdx.x;
    const int tx = tid & 15;
    const int ty = tid >> 4;
    const long long i0 = (long long)blockIdx.x * 128;

#pragma unroll
    for (int l = 0; l < 4; l++) {
        int idx = tid + l * 256;            // 0..1023
        int r  = idx >> 3;                   // 0..127
        int c4 = idx & 7;                    // k/4
        float4 v = make_float4(0.f, 0.f, 0.f, 0.f);
        long long gi = i0 + r;
        if (gi < NE) v = ((const float4*)g_eap)[gi * 8 + c4];
        Ea[c4 * 4 + 0][r] = v.x;
        Ea[c4 * 4 + 1][r] = v.y;
        Ea[c4 * 4 + 2][r] = v.z;
        Ea[c4 * 4 + 3][r] = v.w;
        ((float4*)&Bs[idx >> 5][0])[idx & 31] = ((const float4*)we)[idx];
    }
    __syncthreads();

    u64 acc2[4][8];
#pragma unroll
    for (int i = 0; i < 4; i++)
#pragma unroll
        for (int j = 0; j < 8; j++) acc2[i][j] = 0ULL;

#pragma unroll 8
    for (int k = 0; k < DE; k++) {
        const u64* ap = (const u64*)&Ea[k][ty * 8];
        u64 av[4] = {ap[0], ap[1], ap[2], ap[3]};
        float4 b0 = ((const float4*)&Bs[k][0])[tx * 2];
        float4 b1 = ((const float4*)&Bs[k][0])[tx * 2 + 1];
        u64 bd[8];
        bd[0] = pack2(b0.x, b0.x); bd[1] = pack2(b0.y, b0.y);
        bd[2] = pack2(b0.z, b0.z); bd[3] = pack2(b0.w, b0.w);
        bd[4] = pack2(b1.x, b1.x); bd[5] = pack2(b1.y, b1.y);
        bd[6] = pack2(b1.z, b1.z); bd[7] = pack2(b1.w, b1.w);
#pragma unroll
        for (int i = 0; i < 4; i++)
#pragma unroll
            for (int j = 0; j < 8; j++)
                acc2[i][j] = ffma2(av[i], bd[j], acc2[i][j]);
    }

    // Epilogue: bias + x-gather + relu + segmented reduction over dst runs.
    float4 bb0 = ((const float4*)be)[tx * 2];
    float4 bb1 = ((const float4*)be)[tx * 2 + 1];
    float bvv[8] = {bb0.x, bb0.y, bb0.z, bb0.w, bb1.x, bb1.y, bb1.z, bb1.w};

    int d_cur = -1;
    float sum[8];
#pragma unroll
    for (int rr = 0; rr < 8; rr++) {
        long long gi = i0 + ty * 8 + rr;
        if (gi < NE) {
            int d = g_dstp[gi];
            int src = g_srcp[gi];
            int i2 = rr >> 1;
            float o[8];
#pragma unroll
            for (int j = 0; j < 8; j++) {
                float lo, hi;
                unpack2(acc2[i2][j], lo, hi);
                o[j] = (rr & 1) ? hi : lo;
            }
            float4 xv0 = ((const float4*)xin)[(long long)src * 32 + tx * 2];
            float4 xv1 = ((const float4*)xin)[(long long)src * 32 + tx * 2 + 1];
            float xr[8] = {xv0.x, xv0.y, xv0.z, xv0.w, xv1.x, xv1.y, xv1.z, xv1.w};
            float res[8];
#pragma unroll
            for (int j = 0; j < 8; j++)
                res[j] = fmaxf(o[j] + bvv[j] + xr[j], 0.f);
            if (d != d_cur) {
                if (d_cur >= 0) {
                    float* p = agg + (long long)d_cur * DD + tx * 8;
                    asm volatile("red.global.add.v4.f32 [%0], {%1,%2,%3,%4};"
                                 :: "l"(p), "f"(sum[0]), "f"(sum[1]), "f"(sum[2]), "f"(sum[3]) : "memory");
                    asm volatile("red.global.add.v4.f32 [%0], {%1,%2,%3,%4};"
                                 :: "l"(p + 4), "f"(sum[4]), "f"(sum[5]), "f"(sum[6]), "f"(sum[7]) : "memory");
                }
                d_cur = d;
#pragma unroll
                for (int j = 0; j < 8; j++) sum[j] = res[j];
            } else {
#pragma unroll
                for (int j = 0; j < 8; j++) sum[j] += res[j];
            }
        }
    }
    if (d_cur >= 0) {
        float* p = agg + (long long)d_cur * DD + tx * 8;
        asm volatile("red.global.add.v4.f32 [%0], {%1,%2,%3,%4};"
                     :: "l"(p), "f"(sum[0]), "f"(sum[1]), "f"(sum[2]), "f"(sum[3]) : "memory");
        asm volatile("red.global.add.v4.f32 [%0], {%1,%2,%3,%4};"
                     :: "l"(p + 4), "f"(sum[4]), "f"(sum[5]), "f"(sum[6]), "f"(sum[7]) : "memory");
    }
}

// ---------------------------------------------------------------------------
// float4 copy: agg = src  (seeds the (1+eps)*x term before atomic adds)
// ---------------------------------------------------------------------------
__global__ void copy4_kernel(const float4* __restrict__ s, float4* __restrict__ d, int n4) {
    int i = blockIdx.x * blockDim.x + threadIdx.x;
    if (i < n4) d[i] = s[i];
}

// ===========================================================================
// Tiled SGEMM (f32x2): out[M,128] = act(A[M,128] @ W[128,128] + bias)
// ===========================================================================
template <bool RELU>
__global__ void __launch_bounds__(256, 2)
mlp_gemm(const float* __restrict__ A, const float* __restrict__ W,
         const float* __restrict__ bias, float* __restrict__ out, int M) {
    __shared__ float As[16][128];
    __shared__ float Bs[16][128];

    const int tid = threadIdx.x;
    const int tx = tid & 15;
    const int ty = tid >> 4;
    const int row0 = blockIdx.x * 128;

    u64 acc2[4][8];
#pragma unroll
    for (int i = 0; i < 4; i++)
#pragma unroll
        for (int j = 0; j < 8; j++) acc2[i][j] = 0ULL;

    for (int k0 = 0; k0 < 128; k0 += 16) {
#pragma unroll
        for (int l = 0; l < 2; l++) {
            int idx = tid + l * 256;
            int r  = idx >> 2;
            int c4 = idx & 3;
            float4 v = make_float4(0.f, 0.f, 0.f, 0.f);
            int grow = row0 + r;
            if (grow < M) v = ((const float4*)A)[(long long)grow * 32 + (k0 >> 2) + c4];
            As[c4 * 4 + 0][r] = v.x;
            As[c4 * 4 + 1][r] = v.y;
            As[c4 * 4 + 2][r] = v.z;
            As[c4 * 4 + 3][r] = v.w;
            int k  = idx >> 5;
            int n4 = idx & 31;
            ((float4*)&Bs[k][0])[n4] = ((const float4*)W)[(k0 + k) * 32 + n4];
        }
        __syncthreads();
#pragma unroll
        for (int k = 0; k < 16; k++) {
            const u64* ap = (const u64*)&As[k][ty * 8];
            u64 av[4] = {ap[0], ap[1], ap[2], ap[3]};
            float4 b0 = ((const float4*)&Bs[k][0])[tx * 2];
            float4 b1 = ((const float4*)&Bs[k][0])[tx * 2 + 1];
            u64 bd[8];
            bd[0] = pack2(b0.x, b0.x); bd[1] = pack2(b0.y, b0.y);
            bd[2] = pack2(b0.z, b0.z); bd[3] = pack2(b0.w, b0.w);
            bd[4] = pack2(b1.x, b1.x); bd[5] = pack2(b1.y, b1.y);
            bd[6] = pack2(b1.z, b1.z); bd[7] = pack2(b1.w, b1.w);
#pragma unroll
            for (int i = 0; i < 4; i++)
#pragma unroll
                for (int j = 0; j < 8; j++)
                    acc2[i][j] = ffma2(av[i], bd[j], acc2[i][j]);
        }
        __syncthreads();
    }

    float4 bb0 = ((const float4*)bias)[tx * 2];
    float4 bb1 = ((const float4*)bias)[tx * 2 + 1];
    float bvv[8] = {bb0.x, bb0.y, bb0.z, bb0.w, bb1.x, bb1.y, bb1.z, bb1.w};
#pragma unroll
    for (int i2 = 0; i2 < 4; i2++) {
        float o0[8], o1[8];
#pragma unroll
        for (int j = 0; j < 8; j++) {
            float lo, hi;
            unpack2(acc2[i2][j], lo, hi);
            lo += bvv[j]; hi += bvv[j];
            if (RELU) { lo = fmaxf(lo, 0.f); hi = fmaxf(hi, 0.f); }
            o0[j] = lo; o1[j] = hi;
        }
        int r0 = row0 + ty * 8 + 2 * i2;
        if (r0 < M) {
            float4* po = (float4*)(out + (long long)r0 * DD);
            po[tx * 2]     = make_float4(o0[0], o0[1], o0[2], o0[3]);
            po[tx * 2 + 1] = make_float4(o0[4], o0[5], o0[6], o0[7]);
        }
        if (r0 + 1 < M) {
            float4* po = (float4*)(out + (long long)(r0 + 1) * DD);
            po[tx * 2]     = make_float4(o1[0], o1[1], o1[2], o1[3]);
            po[tx * 2 + 1] = make_float4(o1[4], o1[5], o1[6], o1[7]);
        }
    }
}

// ---------------------------------------------------------------------------
extern "C" void kernel_launch(void* const* d_in, const int* in_sizes, int n_in,
                              void* d_out, int out_size) {
    const float* x    = (const float*)d_in[0];
    const int*   ei   = (const int*)d_in[1];      // int32
    const float* ea   = (const float*)d_in[2];
    const float* w1_0 = (const float*)d_in[3];
    const float* b1_0 = (const float*)d_in[4];
    const float* w2_0 = (const float*)d_in[5];
    const float* b2_0 = (const float*)d_in[6];
    const float* we_0 = (const float*)d_in[7];
    const float* be_0 = (const float*)d_in[8];
    const float* w1_1 = (const float*)d_in[9];
    const float* b1_1 = (const float*)d_in[10];
    const float* w2_1 = (const float*)d_in[11];
    const float* b2_1 = (const float*)d_in[12];
    const float* we_1 = (const float*)d_in[13];
    const float* be_1 = (const float*)d_in[14];
    const float* fc1w = (const float*)d_in[15];
    const float* fc1b = (const float*)d_in[16];
    const float* fc2w = (const float*)d_in[17];
    const float* fc2b = (const float*)d_in[18];
    float* out = (float*)d_out;

    float *agg, *h, *t;
    cudaGetSymbolAddress((void**)&agg, g_agg);
    cudaGetSymbolAddress((void**)&h,   g_h);
    cudaGetSymbolAddress((void**)&t,   g_t);

    const int n4 = NN * (DD / 4);
    const int copyBlocks = (n4 + 255) / 256;
    const int nodeBlocks = (NN + 255) / 256;
    const int edgeThreadBlocks = (NE + 255) / 256;
    const int permBlocks = (int)(((long long)NE * 8 + 255) / 256);
    const int fusedBlocks = (NE + 127) / 128;         // 4688
    const int gemmBlocks = (NN + 127) / 128;          // 391

    // ---- CSR build (once; reused by both layers) ----
    zero_cnt_kernel<<<nodeBlocks, 256>>>();
    hist_kernel<<<edgeThreadBlocks, 256>>>(ei);
    scan_kernel<<<1, 1024>>>();
    scatter_kernel<<<edgeThreadBlocks, 256>>>(ei);
    permute_ea_kernel<<<permBlocks, 256>>>((const float4*)ea);

    // ---- Layer 0 ----
    copy4_kernel<<<copyBlocks, 256>>>((const float4*)x, (float4*)agg, n4);
    edge_fused_kernel<<<fusedBlocks, 256>>>(x, we_0, be_0, agg);
    mlp_gemm<true><<<gemmBlocks, 256>>>(agg, w1_0, b1_0, t, NN);
    mlp_gemm<true><<<gemmBlocks, 256>>>(t, w2_0, b2_0, h, NN);   // + inter-layer relu

    // ---- Layer 1 ----
    copy4_kernel<<<copyBlocks, 256>>>((const float4*)h, (float4*)agg, n4);
    edge_fused_kernel<<<fusedBlocks, 256>>>(h, we_1, be_1, agg);
    mlp_gemm<true><<<gemmBlocks, 256>>>(agg, w1_1, b1_1, t, NN);
    mlp_gemm<true><<<gemmBlocks, 256>>>(t, w2_1, b2_1, h, NN);   // + inter-layer relu

    // ---- Head ----
    mlp_gemm<true><<<gemmBlocks, 256>>>(h, fc1w, fc1b, t, NN);
    mlp_gemm<false><<<gemmBlocks, 256>>>(t, fc2w, fc2b, out, NN);
}